// round 2
// baseline (speedup 1.0000x reference)
#include <cuda_runtime.h>
#include <math.h>

#define BD 8192
#define CD 2048

// Precomputed pair-features.
// gA4[p][row][fg] : float4 {f_{2fg}, f_{2fg}, f_{2fg+1}, f_{2fg+1}}  (duplicated for f32x2 a-operand)
// gB4[p][fg][pc]  : float4 {f_{2fg}(c0), f_{2fg}(c1), f_{2fg+1}(c0), f_{2fg+1}(c1)}  (column pair pc)
__device__ float4 gA4[4 * BD * 2];
__device__ float4 gB4[4 * 2 * (CD / 2)];

union F4U { float4 f; unsigned long long u[2]; };

__global__ void qk_pre(const float* __restrict__ x,
                       const float* __restrict__ c,
                       int B, int C) {
    int t = blockIdx.x * blockDim.x + threadIdx.x;
    if (t < B) {
        float cv[8], sv[8];
        #pragma unroll
        for (int j = 0; j < 8; j++) sincosf(0.5f * x[t * 8 + j], &sv[j], &cv[j]);
        #pragma unroll
        for (int p = 0; p < 4; p++) {
            float f0 = cv[2*p] * cv[2*p+1];
            float f1 = cv[2*p] * sv[2*p+1];
            float f2 = sv[2*p] * cv[2*p+1];
            float f3 = sv[2*p] * sv[2*p+1];
            gA4[p * (2 * BD) + t * 2 + 0] = make_float4(f0, f0, f1, f1);
            gA4[p * (2 * BD) + t * 2 + 1] = make_float4(f2, f2, f3, f3);
        }
    } else if (t < B + C) {
        int col = t - B;
        float cv[8], sv[8];
        #pragma unroll
        for (int j = 0; j < 8; j++) sincosf(0.5f * c[col * 8 + j], &sv[j], &cv[j]);
        int pc = col >> 1, half = col & 1;
        #pragma unroll
        for (int p = 0; p < 4; p++) {
            float f0 = cv[2*p] * cv[2*p+1];
            float f1 = cv[2*p] * sv[2*p+1];
            float f2 = sv[2*p] * cv[2*p+1];
            float f3 = sv[2*p] * sv[2*p+1];
            {
                float* e = (float*)&gB4[(p * 2 + 0) * (CD / 2) + pc];
                e[half] = f0; e[2 + half] = f1;
            }
            {
                float* e = (float*)&gB4[(p * 2 + 1) * (CD / 2) + pc];
                e[half] = f2; e[2 + half] = f3;
            }
        }
    }
}

// Block tile: 128 rows x 128 cols, 256 threads, thread tile 8 rows x 8 cols
// (4 f32x2 column-pairs). 19 f32x2 slots per 2 outputs; zero MOV duplication.
__global__ void __launch_bounds__(256, 2)
qk_fid(float* __restrict__ out, int B, int C) {
    __shared__ float4 sA[4 * 128 * 2];  // [p][r][fg]  16KB
    __shared__ float4 sB[4 * 2 * 64];   // [p][fg][pc]  8KB

    const int tid = threadIdx.x;
    const int row0 = blockIdx.y * 128;
    const int col0 = blockIdx.x * 128;

    // Tile copies: fully linear smem writes, contiguous global chunks.
    #pragma unroll
    for (int k = 0; k < 4; k++)
        sA[k * 256 + tid] = gA4[k * (2 * BD) + row0 * 2 + tid];
    #pragma unroll
    for (int k = 0; k < 2; k++) {
        int idx = tid + k * 256;
        int ch = idx >> 6, i = idx & 63;
        sB[idx] = gB4[ch * (CD / 2) + (col0 >> 1) + i];
    }
    __syncthreads();

    const int ty = tid >> 4;    // 16 row-groups
    const int tx = tid & 15;    // 16 column-pair lanes
    const int rbase = ty * 8;

    unsigned long long acc[8][4];

    #pragma unroll
    for (int p = 0; p < 4; p++) {
        // b operands for this pair: 4 features x 4 column-pairs.
        unsigned long long b[4][4];
        #pragma unroll
        for (int fg = 0; fg < 2; fg++) {
            #pragma unroll
            for (int cp = 0; cp < 4; cp++) {
                F4U v; v.f = sB[(p * 2 + fg) * 64 + tx + 16 * cp];
                b[2 * fg + 0][cp] = v.u[0];
                b[2 * fg + 1][cp] = v.u[1];
            }
        }
        #pragma unroll
        for (int r = 0; r < 8; r++) {
            F4U a01, a23;
            a01.f = sA[(p * 128 + rbase + r) * 2 + 0];
            a23.f = sA[(p * 128 + rbase + r) * 2 + 1];
            unsigned long long a0 = a01.u[0], a1 = a01.u[1];
            unsigned long long a2 = a23.u[0], a3 = a23.u[1];
            #pragma unroll
            for (int cp = 0; cp < 4; cp++) {
                unsigned long long t;
                asm("mul.rn.f32x2 %0, %1, %2;"     : "=l"(t) : "l"(a0), "l"(b[0][cp]));
                asm("fma.rn.f32x2 %0, %1, %2, %3;" : "=l"(t) : "l"(a1), "l"(b[1][cp]), "l"(t));
                asm("fma.rn.f32x2 %0, %1, %2, %3;" : "=l"(t) : "l"(a2), "l"(b[2][cp]), "l"(t));
                asm("fma.rn.f32x2 %0, %1, %2, %3;" : "=l"(t) : "l"(a3), "l"(b[3][cp]), "l"(t));
                if (p == 0) {
                    acc[r][cp] = t;
                } else {
                    asm("mul.rn.f32x2 %0, %1, %2;"
                        : "=l"(acc[r][cp]) : "l"(acc[r][cp]), "l"(t));
                }
            }
        }
    }

    // Epilogue: |value| via packed sign-mask, coalesced STG.64.
    #pragma unroll
    for (int r = 0; r < 8; r++) {
        float* orow = out + (size_t)(row0 + rbase + r) * C + col0 + 2 * tx;
        #pragma unroll
        for (int cp = 0; cp < 4; cp++) {
            unsigned long long v = acc[r][cp] & 0x7FFFFFFF7FFFFFFFull;
            *(unsigned long long*)(orow + 32 * cp) = v;
        }
    }
}

extern "C" void kernel_launch(void* const* d_in, const int* in_sizes, int n_in,
                              void* d_out, int out_size) {
    const float* x = (const float*)d_in[0];
    const float* c = (const float*)d_in[1];
    float* out = (float*)d_out;

    int B = in_sizes[0] / 8;   // 8192
    int C = in_sizes[1] / 8;   // 2048
    if (B > BD) B = BD;
    if (C > CD) C = CD;

    int total = B + C;
    qk_pre<<<(total + 255) / 256, 256>>>(x, c, B, C);

    dim3 grid(C / 128, B / 128);
    qk_fid<<<grid, 256>>>(out, B, C);
}